// round 14
// baseline (speedup 1.0000x reference)
#include <cuda_runtime.h>
#include <cuda_fp16.h>
#include <cstdint>

#define NL 1024
#define NB 32
#define NT 12
#define NF 4
#define NH 64
#define NC 512          // CTAs, 2 links each
#define SHS 88          // sH row stride in halfs (per batch row)
#define SHL (32 * SHS)  // per-link sH halfs

// Scratch (static device globals: allocation-free rule)
__device__ float g_h[2][NL * NH * NB];      // hidden [L][H][B], double buffered (neighbor exchange)
__device__ float g_xT[NT * NL * NF * NB];   // x transposed to [T][L][F][B]
__device__ __half g_wf[NL * 4 * 15 * 256];  // A-fragments: ((l*4+warp)*15 + kit*3 + gate) blocks of 256 half
__device__ int g_flag[NC * 32];             // per-CTA progress flags, 128B stride

// D(16x8,f32) += A(16x16,f16) @ B(16x8,f16)
__device__ __forceinline__ void mma16816(float2& d01, float2& d23,
                                         uint4 a, uint32_t b0, uint32_t b1) {
    asm volatile(
        "mma.sync.aligned.m16n8k16.row.col.f32.f16.f16.f32 "
        "{%0,%1,%2,%3}, {%4,%5,%6,%7}, {%8,%9}, {%0,%1,%2,%3};"
        : "+f"(d01.x), "+f"(d01.y), "+f"(d23.x), "+f"(d23.y)
        : "r"(a.x), "r"(a.y), "r"(a.z), "r"(a.w), "r"(b0), "r"(b1));
}

// HW tanh: single MUFU op (fp32)
__device__ __forceinline__ float tanh_hw(float x) {
    float y;
    asm("tanh.approx.f32 %0, %1;" : "=f"(y) : "f"(x));
    return y;
}
// HW tanh on a pair via f16x2: ONE MUFU op for two values (used for r/z gates)
__device__ __forceinline__ float2 tanh2_hw(float a, float b) {
    uint32_t h, r;
    asm("cvt.rn.f16x2.f32 %0, %1, %2;" : "=r"(h) : "f"(b), "f"(a));  // lo=a, hi=b
    asm("tanh.approx.f16x2 %0, %1;" : "=r"(r) : "r"(h));
    __half2 hr = *(__half2*)&r;
    return make_float2(__low2float(hr), __high2float(hr));
}

// release/acquire flag ops (CG grid-sync pattern)
__device__ __forceinline__ void flag_release(int* p, int v) {
    asm volatile("st.release.gpu.global.s32 [%0], %1;" :: "l"(p), "r"(v) : "memory");
}
__device__ __forceinline__ int flag_acquire(const int* p) {
    int v;
    asm volatile("ld.acquire.gpu.global.s32 %0, [%1];" : "=r"(v) : "l"(p) : "memory");
    return v;
}
__device__ __forceinline__ void prefetch_l1(const void* p) {
    asm volatile("prefetch.global.L1 [%0];" :: "l"(p));
}

// ---------------- prep kernels ----------------

__global__ void prep_x(const float* __restrict__ x) {
    int idx = blockIdx.x * blockDim.x + threadIdx.x;
    if (idx < NC * 32) g_flag[idx] = 0;          // reset wavefront flags each replay
    if (idx >= NT * NL * NF * NB) return;
    int b = idx & 31;
    int f = (idx >> 5) & 3;
    int l = (idx >> 7) & 1023;
    int t = idx >> 17;
    g_xT[idx] = x[((b * NT + t) * NF + f) * NL + l];
}

// hidden-gate weights -> A-fragments (kits 0..3), smem-staged for coalescing.
__global__ void prep_wfrag_h(const float* __restrict__ w_rh, const float* __restrict__ w_uh,
                             const float* __restrict__ w_nh) {
    __shared__ float sm[4096];
    int bid = blockIdx.x;                // l*3 + gate
    int gate = bid % 3, l = bid / 3;
    int tid = threadIdx.x;               // 256
    const float* W = (gate == 0) ? w_rh : (gate == 1) ? w_uh : w_nh;
    const float4* src = (const float4*)(W + l * 4096);
    float4* dsm = (float4*)sm;
#pragma unroll
    for (int i = 0; i < 4; i++) dsm[tid + i * 256] = src[tid + i * 256];
    __syncthreads();
#pragma unroll
    for (int i = 0; i < 2; i++) {
        int e = tid + i * 256;           // 0..511
        int fb = e >> 5;                 // 0..15 : kit*4 + wm
        int kit = fb >> 2, wm = fb & 3;
        int lane = e & 31, gr = lane >> 2, tig = lane & 3;
        uint32_t v[4];
#pragma unroll
        for (int s = 0; s < 4; s++) {
            int row = wm * 16 + gr + ((s & 1) ? 8 : 0);       // gru output k
            int col = kit * 16 + tig * 2 + ((s & 2) ? 8 : 0); // h input
            __half2 h = __floats2half2_rn(sm[col * 64 + row], sm[(col + 1) * 64 + row]);
            v[s] = *(uint32_t*)&h;
        }
        ((uint4*)g_wf)[((l * 4 + wm) * 15 + kit * 3 + gate) * 32 + lane] =
            make_uint4(v[0], v[1], v[2], v[3]);
    }
}

// x-weights + biases -> A-fragments (kit 4).
__global__ void prep_wfrag_x(const float* __restrict__ w_ri, const float* __restrict__ w_ui,
                             const float* __restrict__ w_ni,
                             const float* __restrict__ b_rh, const float* __restrict__ b_ri,
                             const float* __restrict__ b_uh, const float* __restrict__ b_ui,
                             const float* __restrict__ b_ni) {
    int bid = blockIdx.x;                // l*3 + gate
    int gate = bid % 3, l = bid / 3;
    int tid = threadIdx.x;               // 128
    int wm = tid >> 5, lane = tid & 31, gr = lane >> 2, tig = lane & 3;
    const float* Wx = (gate == 0) ? w_ri : (gate == 1) ? w_ui : w_ni;
    uint32_t v[4];
#pragma unroll
    for (int s = 0; s < 4; s++) {
        int row = wm * 16 + gr + ((s & 1) ? 8 : 0);
        int cb = 64 + tig * 2 + ((s & 2) ? 8 : 0);
        float f[2];
#pragma unroll
        for (int j = 0; j < 2; j++) {
            int cc = cb + j;
            float val = 0.0f;
            if (cc < 68) {
                val = Wx[l * 256 + (cc - 64) * 64 + row];
            } else if (cc == 68) {
                if (gate == 0)      val = b_rh[row * NL + l] + b_ri[row * NL + l];
                else if (gate == 1) val = b_uh[row * NL + l] + b_ui[row * NL + l];
                else                val = b_ni[row * NL + l];
            }
            f[j] = val;
        }
        __half2 h = __floats2half2_rn(f[0], f[1]);
        v[s] = *(uint32_t*)&h;
    }
    ((uint4*)g_wf)[((l * 4 + wm) * 15 + 12 + gate) * 32 + lane] =
        make_uint4(v[0], v[1], v[2], v[3]);
}

// ---------------- fused persistent GRU kernel ----------------
// CTA c owns links {2c, 2c+1}; own h(t) lives in registers. Halo links via L2.
// x-GEMM + biases folded into MMA kit4. r/z gates via f16x2 HW tanh (1 MUFU per
// pair), n gate via exact-path f32 HW tanh. A-fragments prefetched into L1 one
// phase ahead. Wavefront handshake: st.release / per-warp ld.acquire spin.

__global__ void __launch_bounds__(128, 4)
fused_kernel(const float* __restrict__ att, const float* __restrict__ b_nh,
             const float* __restrict__ w_fc, const float* __restrict__ b_fc,
             float* __restrict__ out) {
    __shared__ __half sH[2 * SHL];   // per-link B operand: [b][88] halfs

    const int c = blockIdx.x, tid = threadIdx.x;
    const int lane = tid & 31, warp = tid >> 5;
    const int gr = lane >> 2, tig = lane & 3;
    const int k0 = warp * 16 + gr, k1 = k0 + 8;
    const int bq = tig * 2;
    const int l0 = 2 * c;

    // constant sH rows: row 68 = 1.0 (bias), rows 69..79 = 0 (written once)
    for (int e = tid; e < 2 * 32 * 12; e += 128) {
        int li = e / 384, rem = e % 384;
        int b = rem / 12, row = 68 + rem % 12;
        sH[li * SHL + b * SHS + row] = (row == 68) ? __float2half(1.0f) : __half(0);
    }

    // hoisted per-link invariants: attention coeffs + b_nh
    float a0c[2], amc[2], apc[2], bnh[2][2];
#pragma unroll
    for (int li = 0; li < 2; li++) {
        int l = l0 + li;
        a0c[li] = att[l * NL + l];
        amc[li] = (l > 0)      ? att[l * NL + l - 1] : 0.0f;
        apc[li] = (l < NL - 1) ? att[l * NL + l + 1] : 0.0f;
        bnh[li][0] = b_nh[k0 * NL + l];
        bnh[li][1] = b_nh[k1 * NL + l];
    }
    const int lm = (l0 > 0) ? l0 - 1 : l0;           // left halo (coeff 0 at edge)
    const int lp = (l0 + 2 < NL) ? l0 + 2 : l0 + 1;  // right halo (coeff 0 at edge)

    // own hidden state in registers
    float2 o[2][2][4];
#pragma unroll
    for (int li = 0; li < 2; li++)
#pragma unroll
        for (int kr = 0; kr < 2; kr++)
#pragma unroll
            for (int nt = 0; nt < 4; nt++) o[li][kr][nt] = make_float2(0.0f, 0.0f);

    // x staging for step tt -> sH rows 64..67 (no neighbor dependence)
    auto stage_x = [&](int tt) {
#pragma unroll
        for (int i = 0; i < 2; i++) {
            int e = tid + i * 128;
            int li = e >> 7, f = (e >> 5) & 3, b = e & 31;
            sH[li * SHL + b * SHS + 64 + f] =
                __float2half(g_xT[(tt * NL + l0 + li) * 128 + f * 32 + b]);
        }
    };
    // prefetch one link's 15 A-frag blocks into L1 (1 lane per 128B sector)
    auto prefetch_frags = [&](int l) {
        if ((lane & 7) == 0) {
            const char* p = (const char*)((const uint4*)g_wf +
                                          (uint32_t)((l * 4 + warp) * 15) * 32 + lane);
#pragma unroll
            for (int kk = 0; kk < 15; kk++) prefetch_l1(p + kk * 512);
        }
    };

    stage_x(0);   // t=0 rows; made visible by the pre-phase-B __syncthreads

    for (int t = 0; t < NT; t++) {
        const int cur = t & 1, nxt = cur ^ 1;

        // ---- Phase A (t>0): hatt rows; frag prefetch overlaps halo latency ----
        if (t > 0) {
            prefetch_frags(l0);
            const float* hm = g_h[cur] + lm * 2048;
            const float* hp = g_h[cur] + lp * 2048;
#pragma unroll
            for (int kr = 0; kr < 2; kr++) {
                int k = kr ? k1 : k0;
#pragma unroll
                for (int nt = 0; nt < 4; nt++) {
                    int b = nt * 8 + bq;
                    float2 m0 = __ldcg((const float2*)&hm[k * 32 + b]);
                    float2 p1 = __ldcg((const float2*)&hp[k * 32 + b]);
                    float2 h0 = o[0][kr][nt], h1 = o[1][kr][nt];
                    float sx0 = amc[0] * m0.x + a0c[0] * h0.x + apc[0] * h1.x;
                    float sy0 = amc[0] * m0.y + a0c[0] * h0.y + apc[0] * h1.y;
                    float sx1 = amc[1] * h0.x + a0c[1] * h1.x + apc[1] * p1.x;
                    float sy1 = amc[1] * h0.y + a0c[1] * h1.y + apc[1] * p1.y;
                    sH[0 * SHL + b * SHS + k]       = __float2half(sx0);
                    sH[0 * SHL + (b + 1) * SHS + k] = __float2half(sy0);
                    sH[1 * SHL + b * SHS + k]       = __float2half(sx1);
                    sH[1 * SHL + (b + 1) * SHS + k] = __float2half(sy1);
                }
            }
        }
        __syncthreads();   // sH (x + hatt) visible to all warps

        // ---- Phase B: MMA + epilogue, per link ----
#pragma unroll 1
        for (int li = 0; li < 2; li++) {
            const int l = l0 + li;
            const __half* sHl = sH + li * SHL;
            const uint4* wbase = (const uint4*)g_wf + (uint32_t)((l * 4 + warp) * 15) * 32 + lane;
            const float bn0 = bnh[li][0], bn1 = bnh[li][1];

            if (li == 0) prefetch_frags(l0 + 1);   // hide link-1 frag L2 latency

            float2 dR[2][4], dZ[2][4], dN[2][4], xiN[2][4];
#pragma unroll
            for (int nt = 0; nt < 4; nt++) {
                dR[0][nt] = make_float2(0, 0);      dR[1][nt] = make_float2(0, 0);
                dZ[0][nt] = make_float2(0, 0);      dZ[1][nt] = make_float2(0, 0);
                dN[0][nt] = make_float2(bn0, bn0);  dN[1][nt] = make_float2(bn1, bn1);
                xiN[0][nt] = make_float2(0, 0);     xiN[1][nt] = make_float2(0, 0);
            }

            if (t > 0) {
#pragma unroll
                for (int kit = 0; kit < 4; kit++) {
                    uint4 Ar = wbase[(kit * 3 + 0) * 32];
                    uint4 Au = wbase[(kit * 3 + 1) * 32];
                    uint4 An = wbase[(kit * 3 + 2) * 32];
                    const int hb = kit * 16 + bq;
#pragma unroll
                    for (int nt = 0; nt < 4; nt++) {
                        int bb = nt * 8 + gr;
                        uint32_t b0 = *(const uint32_t*)&sHl[bb * SHS + hb];
                        uint32_t b1 = *(const uint32_t*)&sHl[bb * SHS + hb + 8];
                        mma16816(dR[0][nt], dR[1][nt], Ar, b0, b1);
                        mma16816(dZ[0][nt], dZ[1][nt], Au, b0, b1);
                        mma16816(dN[0][nt], dN[1][nt], An, b0, b1);
                    }
                }
            }
            {   // kit 4: x-weights + biases
                uint4 Ar = wbase[(12 + 0) * 32];
                uint4 Au = wbase[(12 + 1) * 32];
                uint4 Ax = wbase[(12 + 2) * 32];
                const int hb = 64 + bq;
#pragma unroll
                for (int nt = 0; nt < 4; nt++) {
                    int bb = nt * 8 + gr;
                    uint32_t b0 = *(const uint32_t*)&sHl[bb * SHS + hb];
                    uint32_t b1 = *(const uint32_t*)&sHl[bb * SHS + hb + 8];
                    mma16816(dR[0][nt], dR[1][nt], Ar, b0, b1);
                    mma16816(dZ[0][nt], dZ[1][nt], Au, b0, b1);
                    mma16816(xiN[0][nt], xiN[1][nt], Ax, b0, b1);
                }
            }

            // epilogue: r/z via f16x2 tanh (1 MUFU per pair), n via f32 tanh
            float* hn = g_h[nxt] + l * 2048;
#pragma unroll
            for (int kr = 0; kr < 2; kr++) {
                int k = kr ? k1 : k0;
#pragma unroll
                for (int nt = 0; nt < 4; nt++) {
                    int b = nt * 8 + bq;
                    float2 hold = o[li][kr][nt];
                    float2 tr = tanh2_hw(0.5f * dR[kr][nt].x, 0.5f * dR[kr][nt].y);
                    float2 tz = tanh2_hw(0.5f * dZ[kr][nt].x, 0.5f * dZ[kr][nt].y);
                    float r0 = fmaf(0.5f, tr.x, 0.5f), r1 = fmaf(0.5f, tr.y, 0.5f);
                    float z0 = fmaf(0.5f, tz.x, 0.5f), z1 = fmaf(0.5f, tz.y, 0.5f);
                    float n0 = tanh_hw(fmaf(r0, dN[kr][nt].x, xiN[kr][nt].x));
                    float n1 = tanh_hw(fmaf(r1, dN[kr][nt].y, xiN[kr][nt].y));
                    float2 nw = make_float2(n0 + z0 * (hold.x - n0),
                                            n1 + z1 * (hold.y - n1));
                    o[li][kr][nt] = nw;
                    *(float2*)&hn[k * 32 + b] = nw;
                }
            }
        }

        // ---- wavefront handshake: release flag, stage next x, per-warp acquire spin ----
        if (t < NT - 1) {
            __syncthreads();                       // all h stores + sH reads of step t done
            if (tid == 0) flag_release(&g_flag[c * 32], t + 1);
            stage_x(t + 1);                        // overlaps the spin below
            if (lane == 0 && c > 0)
                while (flag_acquire(&g_flag[(c - 1) * 32]) <= t) { }
            if (lane == 1 && c < NC - 1)
                while (flag_acquire(&g_flag[(c + 1) * 32]) <= t) { }
            __syncwarp();                          // warp proceeds independently to Phase A
        }
    }

    // ---- fc head (own links; final h in g_h[0] after t=11) ----
    __syncthreads();
    if (tid < 64) {
        int li = tid >> 5, b = tid & 31;
        int l = l0 + li;
        const float* h = g_h[0] + l * 2048;
        float acc = b_fc[l];
#pragma unroll 8
        for (int k = 0; k < NH; k++) acc += __ldcg(&h[k * 32 + b]) * w_fc[l * NH + k];
        out[b * NL + l] = acc;
    }
}

// ---------------- launch ----------------
extern "C" void kernel_launch(void* const* d_in, const int* in_sizes, int n_in,
                              void* d_out, int out_size) {
    const float* x    = (const float*)d_in[0];
    const float* att  = (const float*)d_in[1];
    const float* w_rh = (const float*)d_in[2];
    const float* b_rh = (const float*)d_in[3];
    const float* w_ri = (const float*)d_in[4];
    const float* b_ri = (const float*)d_in[5];
    const float* w_uh = (const float*)d_in[6];
    const float* b_uh = (const float*)d_in[7];
    const float* w_ui = (const float*)d_in[8];
    const float* b_ui = (const float*)d_in[9];
    const float* w_nh = (const float*)d_in[10];
    const float* b_nh = (const float*)d_in[11];
    const float* w_ni = (const float*)d_in[12];
    const float* b_ni = (const float*)d_in[13];
    const float* w_fc = (const float*)d_in[14];
    const float* b_fc = (const float*)d_in[15];

    prep_x<<<6144, 256>>>(x);
    prep_wfrag_h<<<3072, 256>>>(w_rh, w_uh, w_nh);
    prep_wfrag_x<<<3072, 128>>>(w_ri, w_ui, w_ni, b_rh, b_ri, b_uh, b_ui, b_ni);

    fused_kernel<<<NC, 128>>>(att, b_nh, w_fc, b_fc, (float*)d_out);
}

// round 15
// speedup vs baseline: 1.0041x; 1.0041x over previous
#include <cuda_runtime.h>
#include <cuda_fp16.h>
#include <cstdint>

#define NL 1024
#define NB 32
#define NT 12
#define NF 4
#define NH 64
#define NC 512          // CTAs, 2 links each
#define SHS 88          // sH row stride in halfs (per batch row)
#define SHL (32 * SHS)  // per-link sH halfs

// Scratch (static device globals: allocation-free rule)
__device__ float g_h[2][NL * NH * NB];      // hidden [L][H][B], double buffered (neighbor exchange)
__device__ float g_xT[NT * NL * NF * NB];   // x transposed to [T][L][F][B]
__device__ __half g_wf[NL * 4 * 15 * 256];  // A-fragments: ((l*4+warp)*15 + kit*3 + gate) blocks of 256 half
__device__ int g_flag[NC * 32];             // per-CTA progress flags, 128B stride

// D(16x8,f32) += A(16x16,f16) @ B(16x8,f16)
__device__ __forceinline__ void mma16816(float2& d01, float2& d23,
                                         uint4 a, uint32_t b0, uint32_t b1) {
    asm volatile(
        "mma.sync.aligned.m16n8k16.row.col.f32.f16.f16.f32 "
        "{%0,%1,%2,%3}, {%4,%5,%6,%7}, {%8,%9}, {%0,%1,%2,%3};"
        : "+f"(d01.x), "+f"(d01.y), "+f"(d23.x), "+f"(d23.y)
        : "r"(a.x), "r"(a.y), "r"(a.z), "r"(a.w), "r"(b0), "r"(b1));
}

// HW tanh: single MUFU op (fp32)
__device__ __forceinline__ float tanh_hw(float x) {
    float y;
    asm("tanh.approx.f32 %0, %1;" : "=f"(y) : "f"(x));
    return y;
}
// HW tanh on a pair via f16x2: ONE MUFU op for two values (used for r/z gates)
__device__ __forceinline__ float2 tanh2_hw(float a, float b) {
    uint32_t h, r;
    asm("cvt.rn.f16x2.f32 %0, %1, %2;" : "=r"(h) : "f"(b), "f"(a));  // lo=a, hi=b
    asm("tanh.approx.f16x2 %0, %1;" : "=r"(r) : "r"(h));
    __half2 hr = *(__half2*)&r;
    return make_float2(__low2float(hr), __high2float(hr));
}

// release/acquire flag ops (CG grid-sync pattern)
__device__ __forceinline__ void flag_release(int* p, int v) {
    asm volatile("st.release.gpu.global.s32 [%0], %1;" :: "l"(p), "r"(v) : "memory");
}
__device__ __forceinline__ int flag_acquire(const int* p) {
    int v;
    asm volatile("ld.acquire.gpu.global.s32 %0, [%1];" : "=r"(v) : "l"(p) : "memory");
    return v;
}
__device__ __forceinline__ void prefetch_l1(const void* p) {
    asm volatile("prefetch.global.L1 [%0];" :: "l"(p));
}

// ---------------- prep kernels ----------------

__global__ void prep_x(const float* __restrict__ x) {
    int idx = blockIdx.x * blockDim.x + threadIdx.x;
    if (idx < NC * 32) g_flag[idx] = 0;          // reset wavefront flags each replay
    if (idx >= NT * NL * NF * NB) return;
    int b = idx & 31;
    int f = (idx >> 5) & 3;
    int l = (idx >> 7) & 1023;
    int t = idx >> 17;
    g_xT[idx] = x[((b * NT + t) * NF + f) * NL + l];
}

// hidden-gate weights -> A-fragments (kits 0..3), smem-staged for coalescing.
__global__ void prep_wfrag_h(const float* __restrict__ w_rh, const float* __restrict__ w_uh,
                             const float* __restrict__ w_nh) {
    __shared__ float sm[4096];
    int bid = blockIdx.x;                // l*3 + gate
    int gate = bid % 3, l = bid / 3;
    int tid = threadIdx.x;               // 256
    const float* W = (gate == 0) ? w_rh : (gate == 1) ? w_uh : w_nh;
    const float4* src = (const float4*)(W + l * 4096);
    float4* dsm = (float4*)sm;
#pragma unroll
    for (int i = 0; i < 4; i++) dsm[tid + i * 256] = src[tid + i * 256];
    __syncthreads();
#pragma unroll
    for (int i = 0; i < 2; i++) {
        int e = tid + i * 256;           // 0..511
        int fb = e >> 5;                 // 0..15 : kit*4 + wm
        int kit = fb >> 2, wm = fb & 3;
        int lane = e & 31, gr = lane >> 2, tig = lane & 3;
        uint32_t v[4];
#pragma unroll
        for (int s = 0; s < 4; s++) {
            int row = wm * 16 + gr + ((s & 1) ? 8 : 0);       // gru output k
            int col = kit * 16 + tig * 2 + ((s & 2) ? 8 : 0); // h input
            __half2 h = __floats2half2_rn(sm[col * 64 + row], sm[(col + 1) * 64 + row]);
            v[s] = *(uint32_t*)&h;
        }
        ((uint4*)g_wf)[((l * 4 + wm) * 15 + kit * 3 + gate) * 32 + lane] =
            make_uint4(v[0], v[1], v[2], v[3]);
    }
}

// x-weights + biases -> A-fragments (kit 4).
__global__ void prep_wfrag_x(const float* __restrict__ w_ri, const float* __restrict__ w_ui,
                             const float* __restrict__ w_ni,
                             const float* __restrict__ b_rh, const float* __restrict__ b_ri,
                             const float* __restrict__ b_uh, const float* __restrict__ b_ui,
                             const float* __restrict__ b_ni) {
    int bid = blockIdx.x;                // l*3 + gate
    int gate = bid % 3, l = bid / 3;
    int tid = threadIdx.x;               // 128
    int wm = tid >> 5, lane = tid & 31, gr = lane >> 2, tig = lane & 3;
    const float* Wx = (gate == 0) ? w_ri : (gate == 1) ? w_ui : w_ni;
    uint32_t v[4];
#pragma unroll
    for (int s = 0; s < 4; s++) {
        int row = wm * 16 + gr + ((s & 1) ? 8 : 0);
        int cb = 64 + tig * 2 + ((s & 2) ? 8 : 0);
        float f[2];
#pragma unroll
        for (int j = 0; j < 2; j++) {
            int cc = cb + j;
            float val = 0.0f;
            if (cc < 68) {
                val = Wx[l * 256 + (cc - 64) * 64 + row];
            } else if (cc == 68) {
                if (gate == 0)      val = b_rh[row * NL + l] + b_ri[row * NL + l];
                else if (gate == 1) val = b_uh[row * NL + l] + b_ui[row * NL + l];
                else                val = b_ni[row * NL + l];
            }
            f[j] = val;
        }
        __half2 h = __floats2half2_rn(f[0], f[1]);
        v[s] = *(uint32_t*)&h;
    }
    ((uint4*)g_wf)[((l * 4 + wm) * 15 + 12 + gate) * 32 + lane] =
        make_uint4(v[0], v[1], v[2], v[3]);
}

// ---------------- fused persistent GRU kernel ----------------
// CTA c owns links {2c, 2c+1}; own h(t) lives in registers. Halo links via L2.
// x-GEMM + biases folded into MMA kit4. r/z gates via f16x2 HW tanh (1 MUFU per
// pair), n gate via exact-path f32 HW tanh. A-fragments prefetched into L1 one
// phase ahead. Wavefront handshake: st.release / per-warp ld.acquire spin.

__global__ void __launch_bounds__(128, 4)
fused_kernel(const float* __restrict__ att, const float* __restrict__ b_nh,
             const float* __restrict__ w_fc, const float* __restrict__ b_fc,
             float* __restrict__ out) {
    __shared__ __half sH[2 * SHL];   // per-link B operand: [b][88] halfs

    const int c = blockIdx.x, tid = threadIdx.x;
    const int lane = tid & 31, warp = tid >> 5;
    const int gr = lane >> 2, tig = lane & 3;
    const int k0 = warp * 16 + gr, k1 = k0 + 8;
    const int bq = tig * 2;
    const int l0 = 2 * c;

    // constant sH rows: row 68 = 1.0 (bias), rows 69..79 = 0 (written once)
    for (int e = tid; e < 2 * 32 * 12; e += 128) {
        int li = e / 384, rem = e % 384;
        int b = rem / 12, row = 68 + rem % 12;
        sH[li * SHL + b * SHS + row] = (row == 68) ? __float2half(1.0f) : __half(0);
    }

    // hoisted per-link invariants: attention coeffs + b_nh
    float a0c[2], amc[2], apc[2], bnh[2][2];
#pragma unroll
    for (int li = 0; li < 2; li++) {
        int l = l0 + li;
        a0c[li] = att[l * NL + l];
        amc[li] = (l > 0)      ? att[l * NL + l - 1] : 0.0f;
        apc[li] = (l < NL - 1) ? att[l * NL + l + 1] : 0.0f;
        bnh[li][0] = b_nh[k0 * NL + l];
        bnh[li][1] = b_nh[k1 * NL + l];
    }
    const int lm = (l0 > 0) ? l0 - 1 : l0;           // left halo (coeff 0 at edge)
    const int lp = (l0 + 2 < NL) ? l0 + 2 : l0 + 1;  // right halo (coeff 0 at edge)

    // own hidden state in registers
    float2 o[2][2][4];
#pragma unroll
    for (int li = 0; li < 2; li++)
#pragma unroll
        for (int kr = 0; kr < 2; kr++)
#pragma unroll
            for (int nt = 0; nt < 4; nt++) o[li][kr][nt] = make_float2(0.0f, 0.0f);

    // x staging for step tt -> sH rows 64..67 (no neighbor dependence)
    auto stage_x = [&](int tt) {
#pragma unroll
        for (int i = 0; i < 2; i++) {
            int e = tid + i * 128;
            int li = e >> 7, f = (e >> 5) & 3, b = e & 31;
            sH[li * SHL + b * SHS + 64 + f] =
                __float2half(g_xT[(tt * NL + l0 + li) * 128 + f * 32 + b]);
        }
    };
    // prefetch one link's 15 A-frag blocks into L1 (1 lane per 128B sector)
    auto prefetch_frags = [&](int l) {
        if ((lane & 7) == 0) {
            const char* p = (const char*)((const uint4*)g_wf +
                                          (uint32_t)((l * 4 + warp) * 15) * 32 + lane);
#pragma unroll
            for (int kk = 0; kk < 15; kk++) prefetch_l1(p + kk * 512);
        }
    };

    stage_x(0);   // t=0 rows; made visible by the pre-phase-B __syncthreads

    for (int t = 0; t < NT; t++) {
        const int cur = t & 1, nxt = cur ^ 1;

        // ---- Phase A (t>0): hatt rows; frag prefetch overlaps halo latency ----
        if (t > 0) {
            prefetch_frags(l0);
            const float* hm = g_h[cur] + lm * 2048;
            const float* hp = g_h[cur] + lp * 2048;
#pragma unroll
            for (int kr = 0; kr < 2; kr++) {
                int k = kr ? k1 : k0;
#pragma unroll
                for (int nt = 0; nt < 4; nt++) {
                    int b = nt * 8 + bq;
                    float2 m0 = __ldcg((const float2*)&hm[k * 32 + b]);
                    float2 p1 = __ldcg((const float2*)&hp[k * 32 + b]);
                    float2 h0 = o[0][kr][nt], h1 = o[1][kr][nt];
                    float sx0 = amc[0] * m0.x + a0c[0] * h0.x + apc[0] * h1.x;
                    float sy0 = amc[0] * m0.y + a0c[0] * h0.y + apc[0] * h1.y;
                    float sx1 = amc[1] * h0.x + a0c[1] * h1.x + apc[1] * p1.x;
                    float sy1 = amc[1] * h0.y + a0c[1] * h1.y + apc[1] * p1.y;
                    sH[0 * SHL + b * SHS + k]       = __float2half(sx0);
                    sH[0 * SHL + (b + 1) * SHS + k] = __float2half(sy0);
                    sH[1 * SHL + b * SHS + k]       = __float2half(sx1);
                    sH[1 * SHL + (b + 1) * SHS + k] = __float2half(sy1);
                }
            }
        }
        __syncthreads();   // sH (x + hatt) visible to all warps

        // ---- Phase B: MMA + epilogue, per link ----
#pragma unroll 1
        for (int li = 0; li < 2; li++) {
            const int l = l0 + li;
            const __half* sHl = sH + li * SHL;
            const uint4* wbase = (const uint4*)g_wf + (uint32_t)((l * 4 + warp) * 15) * 32 + lane;
            const float bn0 = bnh[li][0], bn1 = bnh[li][1];

            if (li == 0) prefetch_frags(l0 + 1);   // hide link-1 frag L2 latency

            float2 dR[2][4], dZ[2][4], dN[2][4], xiN[2][4];
#pragma unroll
            for (int nt = 0; nt < 4; nt++) {
                dR[0][nt] = make_float2(0, 0);      dR[1][nt] = make_float2(0, 0);
                dZ[0][nt] = make_float2(0, 0);      dZ[1][nt] = make_float2(0, 0);
                dN[0][nt] = make_float2(bn0, bn0);  dN[1][nt] = make_float2(bn1, bn1);
                xiN[0][nt] = make_float2(0, 0);     xiN[1][nt] = make_float2(0, 0);
            }

            if (t > 0) {
#pragma unroll
                for (int kit = 0; kit < 4; kit++) {
                    uint4 Ar = wbase[(kit * 3 + 0) * 32];
                    uint4 Au = wbase[(kit * 3 + 1) * 32];
                    uint4 An = wbase[(kit * 3 + 2) * 32];
                    const int hb = kit * 16 + bq;
#pragma unroll
                    for (int nt = 0; nt < 4; nt++) {
                        int bb = nt * 8 + gr;
                        uint32_t b0 = *(const uint32_t*)&sHl[bb * SHS + hb];
                        uint32_t b1 = *(const uint32_t*)&sHl[bb * SHS + hb + 8];
                        mma16816(dR[0][nt], dR[1][nt], Ar, b0, b1);
                        mma16816(dZ[0][nt], dZ[1][nt], Au, b0, b1);
                        mma16816(dN[0][nt], dN[1][nt], An, b0, b1);
                    }
                }
            }
            {   // kit 4: x-weights + biases
                uint4 Ar = wbase[(12 + 0) * 32];
                uint4 Au = wbase[(12 + 1) * 32];
                uint4 Ax = wbase[(12 + 2) * 32];
                const int hb = 64 + bq;
#pragma unroll
                for (int nt = 0; nt < 4; nt++) {
                    int bb = nt * 8 + gr;
                    uint32_t b0 = *(const uint32_t*)&sHl[bb * SHS + hb];
                    uint32_t b1 = *(const uint32_t*)&sHl[bb * SHS + hb + 8];
                    mma16816(dR[0][nt], dR[1][nt], Ar, b0, b1);
                    mma16816(dZ[0][nt], dZ[1][nt], Au, b0, b1);
                    mma16816(xiN[0][nt], xiN[1][nt], Ax, b0, b1);
                }
            }

            // epilogue: r/z via f16x2 tanh (1 MUFU per pair), n via f32 tanh
            float* hn = g_h[nxt] + l * 2048;
#pragma unroll
            for (int kr = 0; kr < 2; kr++) {
                int k = kr ? k1 : k0;
#pragma unroll
                for (int nt = 0; nt < 4; nt++) {
                    int b = nt * 8 + bq;
                    float2 hold = o[li][kr][nt];
                    float2 tr = tanh2_hw(0.5f * dR[kr][nt].x, 0.5f * dR[kr][nt].y);
                    float2 tz = tanh2_hw(0.5f * dZ[kr][nt].x, 0.5f * dZ[kr][nt].y);
                    float r0 = fmaf(0.5f, tr.x, 0.5f), r1 = fmaf(0.5f, tr.y, 0.5f);
                    float z0 = fmaf(0.5f, tz.x, 0.5f), z1 = fmaf(0.5f, tz.y, 0.5f);
                    float n0 = tanh_hw(fmaf(r0, dN[kr][nt].x, xiN[kr][nt].x));
                    float n1 = tanh_hw(fmaf(r1, dN[kr][nt].y, xiN[kr][nt].y));
                    float2 nw = make_float2(n0 + z0 * (hold.x - n0),
                                            n1 + z1 * (hold.y - n1));
                    o[li][kr][nt] = nw;
                    *(float2*)&hn[k * 32 + b] = nw;
                }
            }
        }

        // ---- wavefront handshake: release flag, stage next x, per-warp acquire spin ----
        if (t < NT - 1) {
            __syncthreads();                       // all h stores + sH reads of step t done
            if (tid == 0) flag_release(&g_flag[c * 32], t + 1);
            stage_x(t + 1);                        // overlaps the spin below
            if (lane == 0 && c > 0)
                while (flag_acquire(&g_flag[(c - 1) * 32]) <= t) { }
            if (lane == 1 && c < NC - 1)
                while (flag_acquire(&g_flag[(c + 1) * 32]) <= t) { }
            __syncwarp();                          // warp proceeds independently to Phase A
        }
    }

    // ---- fc head (own links; final h in g_h[0] after t=11) ----
    __syncthreads();
    if (tid < 64) {
        int li = tid >> 5, b = tid & 31;
        int l = l0 + li;
        const float* h = g_h[0] + l * 2048;
        float acc = b_fc[l];
#pragma unroll 8
        for (int k = 0; k < NH; k++) acc += __ldcg(&h[k * 32 + b]) * w_fc[l * NH + k];
        out[b * NL + l] = acc;
    }
}

// ---------------- launch ----------------
extern "C" void kernel_launch(void* const* d_in, const int* in_sizes, int n_in,
                              void* d_out, int out_size) {
    const float* x    = (const float*)d_in[0];
    const float* att  = (const float*)d_in[1];
    const float* w_rh = (const float*)d_in[2];
    const float* b_rh = (const float*)d_in[3];
    const float* w_ri = (const float*)d_in[4];
    const float* b_ri = (const float*)d_in[5];
    const float* w_uh = (const float*)d_in[6];
    const float* b_uh = (const float*)d_in[7];
    const float* w_ui = (const float*)d_in[8];
    const float* b_ui = (const float*)d_in[9];
    const float* w_nh = (const float*)d_in[10];
    const float* b_nh = (const float*)d_in[11];
    const float* w_ni = (const float*)d_in[12];
    const float* b_ni = (const float*)d_in[13];
    const float* w_fc = (const float*)d_in[14];
    const float* b_fc = (const float*)d_in[15];

    prep_x<<<6144, 256>>>(x);
    prep_wfrag_h<<<3072, 256>>>(w_rh, w_uh, w_nh);
    prep_wfrag_x<<<3072, 128>>>(w_ri, w_ui, w_ni, b_rh, b_ri, b_uh, b_ui, b_ni);

    fused_kernel<<<NC, 128>>>(att, b_nh, w_fc, b_fc, (float*)d_out);
}